// round 15
// baseline (speedup 1.0000x reference)
#include <cuda_runtime.h>

#define NBINS   6144
#define N_LEV   1024
#define XMIN_F  (-4.25f)
#define XMAX_F  (4.25f)

// ---------------------------------------------------------------------------
// Exact reference nearest-index (searchsorted 'left' + abs-distance compare).
// ---------------------------------------------------------------------------
__device__ __forceinline__ int nidx_exact_s(float x, const float* __restrict__ grid)
{
    int l = 0, r = N_LEV;                 // first i with grid[i] >= x
    while (l < r) {
        int m = (l + r) >> 1;
        if (grid[m] < x) l = m + 1; else r = m;
    }
    int idx = l < 1 ? 1 : (l > N_LEV - 1 ? N_LEV - 1 : l);
    float left  = grid[idx - 1];
    float right = grid[idx];
    return (fabsf(x - left) < fabsf(x - right)) ? idx - 1 : idx;
}

// Monotone walk form of nidx: advance while the nearest-compare predicate
// says "not yet". Identical to nidx_exact_s for all x (ties -> right,
// end clamps included), given sorted distinct levels.
__device__ __forceinline__ int nidx_walk(float x, int idx,
                                         const float* __restrict__ grid)
{
    while (idx < N_LEV - 1 &&
           !(fabsf(x - grid[idx]) < fabsf(x - grid[idx + 1])))
        ++idx;
    return idx;
}

// Exact largest float x for which the reference picks the left level of the
// pair (l, r). pred(x) = |x-l| < |x-r| is monotone true->false in x, so fp
// bisection down to adjacent floats yields the bit-exact threshold.
__device__ __forceinline__ float thr_exact(float l, float r)
{
    if (!(l < r)) return __uint_as_float(0xFF800000u);  // -inf: always right
    float a = l, c = r;
    for (int it = 0; it < 64; ++it) {
        float m = 0.5f * (a + c);
        if (!(m > a && m < c)) break;                   // adjacent -> done
        if (fabsf(m - l) < fabsf(m - r)) a = m; else c = m;
    }
    return a;
}

// ---------------------------------------------------------------------------
// Branchless hot path: one LDS.128 per element, f32 outputs (exact).
// rec = {thr_bits, outL_f32, outR_f32, flag}.
//   flag=0, thr=+inf : pure bin (outL == outR)
//   flag=0, thr finite: one boundary; (x <= thr) ? outL : outR (thr exact)
//   flag=1           : >=2 boundaries (rare, ~0.1% mass) -> bounded walk
// ---------------------------------------------------------------------------
__device__ __forceinline__ float eval_one(float x,
                                          const uint4* __restrict__ s_bins,
                                          const float* __restrict__ s_grid,
                                          const float* __restrict__ s_lut)
{
    const float scale = (float)NBINS / (XMAX_F - XMIN_F);
    const float offs  = -XMIN_F * scale;
    float xc = fmaxf(x, XMIN_F);
    int j = (int)fmaf(xc, scale, offs);            // FFMA + F2I
    j = j > NBINS - 1 ? NBINS - 1 : j;             // IMNMX
    uint4 rec = s_bins[j];                         // LDS.128
    float res = (x <= __uint_as_float(rec.x)) ? __uint_as_float(rec.y)
                                              : __uint_as_float(rec.z);
    if (rec.w) {                                   // rare bounded walk
        int lo = (int)(rec.y & 0xFFFFu);
        float gl = s_grid[lo];
        int hi = (int)(rec.y >> 16);
        while (lo < hi) {
            float gr = s_grid[lo + 1];
            if (fabsf(x - gl) < fabsf(x - gr)) break;   // exact tie-break
            ++lo; gl = gr;
        }
        res = s_lut[lo];
    }
    return res;
}

#define SMEM_BYTES (NBINS * 16 + 2 * N_LEV * 4)

// ---------------------------------------------------------------------------
// Single fused kernel, 2 CTAs/SM (104KB smem each -> 64 warps/SM).
// Prologue per CTA:
//   1) grid = h[:,0]; lut[i] = chain output (exact reference semantics)
//   2) bin table: 6 contiguous bins/thread; ONE binary search for the first
//      widened edge, then monotone walks for every subsequent edge.
// Main loop: coalesced float4 streaming, branchless 16B-record lookups.
// ---------------------------------------------------------------------------
__global__ void __launch_bounds__(1024, 2)
ps_act(const float* __restrict__ h,  const float* __restrict__ d,
       const float* __restrict__ T,  const float* __restrict__ bscal,
       const float4* __restrict__ xin, float4* __restrict__ oout,
       int n4, const float* __restrict__ xs, float* __restrict__ os, int n)
{
    extern __shared__ unsigned char smem_raw[];
    uint4* const s_bins = (uint4*)smem_raw;
    float* const s_grid = (float*)(s_bins + NBINS);
    float* const s_lut  = s_grid + N_LEV;

    const int t0 = threadIdx.x;               // 1024 threads == N_LEV

    // ---- Prologue 1: grid + lut -------------------------------------------
    {
        float hv[9];
#pragma unroll
        for (int t = 0; t < 9; ++t) hv[t] = h[t0 * 9 + t];  // independent loads
        float v = hv[0];
        s_grid[t0] = v;
        float out = 0.0f;
#pragma unroll
        for (int t = 1; t <= 8; ++t) {
            if (v - T[t] >= 0.0f) out += d[t];
            if (t != 8) v = hv[t + 1];
        }
        s_lut[t0] = out - bscal[0];
    }
    __syncthreads();

    // ---- Prologue 2: bin table (search once, then walk) -------------------
    // Widened edges (+-0.25*W >> fp slop of the main-loop fmaf quantizer)
    // guarantee nidx(x) in [lo, hi] for every x mapping to bin j; nidx is
    // monotone so lo/hi advance with the edges -> cheap forward walks.
    {
        const float W   = (XMAX_F - XMIN_F) / (float)NBINS;
        const int   BPT = NBINS / 1024;       // 6 contiguous bins per thread
        const int   j0  = t0 * BPT;

        int lo = nidx_exact_s(XMIN_F + (float)j0 * W - 0.25f * W, s_grid);
#pragma unroll 1
        for (int j = j0; j < j0 + BPT; ++j) {
            float eRw = XMIN_F + (float)(j + 1) * W + 0.25f * W;
            int hi = nidx_walk(eRw, lo, s_grid);
            uint4 rec;
            if (hi == lo) {
                rec.x = 0x7F800000u;                  // +inf: always left
                rec.y = __float_as_uint(s_lut[lo]);
                rec.z = rec.y;
                rec.w = 0u;
            } else if (hi == lo + 1) {
                rec.x = __float_as_uint(thr_exact(s_grid[lo], s_grid[hi]));
                rec.y = __float_as_uint(s_lut[lo]);
                rec.z = __float_as_uint(s_lut[hi]);
                rec.w = 0u;
            } else {
                rec.x = 0u;                           // walk fallback
                rec.y = (unsigned)lo | ((unsigned)hi << 16);
                rec.z = 0u;
                rec.w = 1u;
            }
            s_bins[j] = rec;
            float eLn = XMIN_F + (float)(j + 1) * W - 0.25f * W;
            lo = nidx_walk(eLn, lo, s_grid);          // next bin's lo
        }
    }
    __syncthreads();

    // ---- Main loop --------------------------------------------------------
    const int tid = blockIdx.x * blockDim.x + t0;
    const int nt  = gridDim.x * blockDim.x;

    // Coalesced unroll-2 at offsets (i, i+nt): every LDG.128/STG.128 is a
    // fully-coalesced 512B warp transaction; two loads in flight per thread.
    int i = tid;
    for (; i + nt < n4; i += 2 * nt) {
        float4 a = xin[i];
        float4 c = xin[i + nt];
        float4 ra, rc;
        ra.x = eval_one(a.x, s_bins, s_grid, s_lut);
        ra.y = eval_one(a.y, s_bins, s_grid, s_lut);
        ra.z = eval_one(a.z, s_bins, s_grid, s_lut);
        ra.w = eval_one(a.w, s_bins, s_grid, s_lut);
        rc.x = eval_one(c.x, s_bins, s_grid, s_lut);
        rc.y = eval_one(c.y, s_bins, s_grid, s_lut);
        rc.z = eval_one(c.z, s_bins, s_grid, s_lut);
        rc.w = eval_one(c.w, s_bins, s_grid, s_lut);
        oout[i]      = ra;
        oout[i + nt] = rc;
    }
    if (i < n4) {
        float4 a = xin[i];
        float4 ra;
        ra.x = eval_one(a.x, s_bins, s_grid, s_lut);
        ra.y = eval_one(a.y, s_bins, s_grid, s_lut);
        ra.z = eval_one(a.z, s_bins, s_grid, s_lut);
        ra.w = eval_one(a.w, s_bins, s_grid, s_lut);
        oout[i] = ra;
    }

    // scalar tail (empty for this shape)
    for (int k = n4 * 4 + tid; k < n; k += nt)
        os[k] = eval_one(xs[k], s_bins, s_grid, s_lut);
}

// ---------------------------------------------------------------------------
extern "C" void kernel_launch(void* const* d_in, const int* in_sizes, int n_in,
                              void* d_out, int out_size)
{
    const float* x = (const float*)d_in[0];
    const float* h = (const float*)d_in[1];
    const float* d = (const float*)d_in[2];
    const float* T = (const float*)d_in[3];
    const float* b = (const float*)d_in[4];
    float* out = (float*)d_out;
    int n  = in_sizes[0];
    int n4 = n >> 2;

    cudaFuncSetAttribute(ps_act,
                         cudaFuncAttributeMaxDynamicSharedMemorySize, SMEM_BYTES);

    ps_act<<<304, 1024, SMEM_BYTES>>>(h, d, T, b,
                                      (const float4*)x, (float4*)out,
                                      n4, x, out, n);
}

// round 16
// speedup vs baseline: 1.1135x; 1.1135x over previous
#include <cuda_runtime.h>

#define NBINS   8192
#define N_LEV   1024
#define XMIN_F  (-4.25f)
#define XMAX_F  (4.25f)

// Round-nearest magic quantizer: j = float_bits(fmaf(xc, SCALE, OFFC)) & 0x3FFFFF
//   SCALE = NBINS/8.5, OFFC = 2^23*1.5 + NBINS/2 (both exact in f32).
// Bin j covers v = x*SCALE + NBINS/2 in (j-0.5, j+0.5); prep edges use the
// same convention with +-0.25*W widening to absorb all fp slop.
#define SCALE_F ((float)NBINS / (XMAX_F - XMIN_F))
#define OFFC_F  (12582912.0f + (float)(NBINS / 2))

// ---------------------------------------------------------------------------
// Exact reference nearest-index (searchsorted 'left' + abs-distance compare).
// ---------------------------------------------------------------------------
__device__ __forceinline__ int nidx_exact_s(float x, const float* __restrict__ grid)
{
    int l = 0, r = N_LEV;                 // first i with grid[i] >= x
    while (l < r) {
        int m = (l + r) >> 1;
        if (grid[m] < x) l = m + 1; else r = m;
    }
    int idx = l < 1 ? 1 : (l > N_LEV - 1 ? N_LEV - 1 : l);
    float left  = grid[idx - 1];
    float right = grid[idx];
    return (fabsf(x - left) < fabsf(x - right)) ? idx - 1 : idx;
}

// Monotone walk form of nidx (identical result; cheap for advancing edges).
__device__ __forceinline__ int nidx_walk(float x, int idx,
                                         const float* __restrict__ grid)
{
    while (idx < N_LEV - 1 &&
           !(fabsf(x - grid[idx]) < fabsf(x - grid[idx + 1])))
        ++idx;
    return idx;
}

// Exact largest float x for which the reference picks the left level of the
// pair (l, r): fp bisection on the monotone predicate |x-l| < |x-r|.
__device__ __forceinline__ float thr_exact(float l, float r)
{
    if (!(l < r)) return __uint_as_float(0xFF800000u);  // -inf: always right
    float a = l, c = r;
    for (int it = 0; it < 64; ++it) {
        float m = 0.5f * (a + c);
        if (!(m > a && m < c)) break;                   // adjacent -> done
        if (fabsf(m - l) < fabsf(m - r)) a = m; else c = m;
    }
    return a;
}

#define SMEM_BYTES (NBINS * 16 + 2 * N_LEV * 4)

// ---------------------------------------------------------------------------
// Single fused kernel, 1 CTA/SM (136KB smem). Prologue per CTA:
//   1) grid = h[:,0]; lut[i] = chain output (exact reference semantics)
//   2) bin table: 8 contiguous bins/thread; ONE binary search for the first
//      widened edge, then monotone walks for every subsequent edge.
// rec = {thr_bits, outL_f32, outR_f32, flag}:
//   flag=0, thr=+inf : pure bin;  flag=0 finite thr: (x<=thr)?outL:outR
//   flag=1           : >=2 boundaries (rare) -> bounded walk; rec.y=lo|hi<<16
// Main loop: coalesced float4 streaming; 8 branchless evals + ONE guarded
// fixup branch per iteration (instead of 8).
// ---------------------------------------------------------------------------
__global__ void __launch_bounds__(1024, 1)
ps_act(const float* __restrict__ h,  const float* __restrict__ d,
       const float* __restrict__ T,  const float* __restrict__ bscal,
       const float4* __restrict__ xin, float4* __restrict__ oout,
       int n4, const float* __restrict__ xs, float* __restrict__ os, int n)
{
    extern __shared__ unsigned char smem_raw[];
    uint4* const s_bins = (uint4*)smem_raw;
    float* const s_grid = (float*)(s_bins + NBINS);
    float* const s_lut  = s_grid + N_LEV;

    const int t0 = threadIdx.x;               // 1024 threads == N_LEV

    // ---- Prologue 1: grid + lut -------------------------------------------
    {
        float hv[9];
#pragma unroll
        for (int t = 0; t < 9; ++t) hv[t] = h[t0 * 9 + t];  // independent loads
        float v = hv[0];
        s_grid[t0] = v;
        float out = 0.0f;
#pragma unroll
        for (int t = 1; t <= 8; ++t) {
            if (v - T[t] >= 0.0f) out += d[t];
            if (t != 8) v = hv[t + 1];
        }
        s_lut[t0] = out - bscal[0];
    }
    __syncthreads();

    // ---- Prologue 2: bin table (search once, then walk) -------------------
    // Round-nearest bin j spans [(j-0.5)W, (j+0.5)W) + XMIN; widen by 0.25W.
    {
        const float W   = (XMAX_F - XMIN_F) / (float)NBINS;
        const int   BPT = NBINS / 1024;       // 8 contiguous bins per thread
        const int   j0  = t0 * BPT;

        int lo = nidx_exact_s(XMIN_F + ((float)j0 - 0.75f) * W, s_grid);
#pragma unroll 1
        for (int j = j0; j < j0 + BPT; ++j) {
            float eRw = XMIN_F + ((float)j + 0.75f) * W;
            int hi = nidx_walk(eRw, lo, s_grid);
            uint4 rec;
            if (hi == lo) {
                rec.x = 0x7F800000u;                  // +inf: always left
                rec.y = __float_as_uint(s_lut[lo]);
                rec.z = rec.y;
                rec.w = 0u;
            } else if (hi == lo + 1) {
                rec.x = __float_as_uint(thr_exact(s_grid[lo], s_grid[hi]));
                rec.y = __float_as_uint(s_lut[lo]);
                rec.z = __float_as_uint(s_lut[hi]);
                rec.w = 0u;
            } else {
                rec.x = 0u;                           // walk fallback
                rec.y = (unsigned)lo | ((unsigned)hi << 16);
                rec.z = 0u;
                rec.w = 1u;
            }
            s_bins[j] = rec;
            float eLn = XMIN_F + ((float)(j + 1) - 0.75f) * W;
            lo = nidx_walk(eLn, lo, s_grid);          // next bin's lo
        }
    }
    __syncthreads();

    // ---- Main loop --------------------------------------------------------
    const int tid = blockIdx.x * blockDim.x + t0;
    const int nt  = gridDim.x * blockDim.x;

    int i = tid;
    for (; i + nt < n4; i += 2 * nt) {
        float4 a = xin[i];
        float4 c = xin[i + nt];
        float xv[8] = {a.x, a.y, a.z, a.w, c.x, c.y, c.z, c.w};
        float rv[8];
        unsigned wv[8];
        unsigned anyw = 0u;
#pragma unroll
        for (int e = 0; e < 8; ++e) {
            float xc = fmaxf(xv[e], XMIN_F);                 // FMNMX
            int bits = __float_as_int(fmaf(xc, SCALE_F, OFFC_F)); // FFMA
            int j = bits & 0x3FFFFF;                         // LOP3
            j = j > NBINS - 1 ? NBINS - 1 : j;               // IMNMX
            uint4 rec = s_bins[j];                           // LDS.128
            rv[e] = (xv[e] <= __uint_as_float(rec.x))
                        ? __uint_as_float(rec.y)
                        : __uint_as_float(rec.z);            // FSETP+FSEL
            wv[e] = rec.w ? rec.y : 0u;                      // SEL
            anyw |= rec.w;                                   // LOP
        }
        if (anyw) {                                          // one branch / 8
#pragma unroll
            for (int e = 0; e < 8; ++e) {
                if (wv[e]) {
                    int lo = (int)(wv[e] & 0xFFFFu);
                    int hi = (int)(wv[e] >> 16);
                    float gl = s_grid[lo];
                    while (lo < hi) {
                        float gr = s_grid[lo + 1];
                        if (fabsf(xv[e] - gl) < fabsf(xv[e] - gr)) break;
                        ++lo; gl = gr;                       // exact tie-break
                    }
                    rv[e] = s_lut[lo];
                }
            }
        }
        oout[i]      = make_float4(rv[0], rv[1], rv[2], rv[3]);
        oout[i + nt] = make_float4(rv[4], rv[5], rv[6], rv[7]);
    }
    if (i < n4) {
        float4 a = xin[i];
        float xv[4] = {a.x, a.y, a.z, a.w};
        float rv[4];
#pragma unroll
        for (int e = 0; e < 4; ++e) {
            float xc = fmaxf(xv[e], XMIN_F);
            int bits = __float_as_int(fmaf(xc, SCALE_F, OFFC_F));
            int j = bits & 0x3FFFFF;
            j = j > NBINS - 1 ? NBINS - 1 : j;
            uint4 rec = s_bins[j];
            float res = (xv[e] <= __uint_as_float(rec.x))
                            ? __uint_as_float(rec.y)
                            : __uint_as_float(rec.z);
            if (rec.w) {
                int lo = (int)(rec.y & 0xFFFFu);
                int hi = (int)(rec.y >> 16);
                float gl = s_grid[lo];
                while (lo < hi) {
                    float gr = s_grid[lo + 1];
                    if (fabsf(xv[e] - gl) < fabsf(xv[e] - gr)) break;
                    ++lo; gl = gr;
                }
                res = s_lut[lo];
            }
            rv[e] = res;
        }
        oout[i] = make_float4(rv[0], rv[1], rv[2], rv[3]);
    }

    // scalar tail (empty for this shape)
    for (int k = n4 * 4 + tid; k < n; k += nt) {
        float x = xs[k];
        float xc = fmaxf(x, XMIN_F);
        int bits = __float_as_int(fmaf(xc, SCALE_F, OFFC_F));
        int j = bits & 0x3FFFFF;
        j = j > NBINS - 1 ? NBINS - 1 : j;
        uint4 rec = s_bins[j];
        float res = (x <= __uint_as_float(rec.x)) ? __uint_as_float(rec.y)
                                                  : __uint_as_float(rec.z);
        if (rec.w) {
            int lo = (int)(rec.y & 0xFFFFu);
            int hi = (int)(rec.y >> 16);
            float gl = s_grid[lo];
            while (lo < hi) {
                float gr = s_grid[lo + 1];
                if (fabsf(x - gl) < fabsf(x - gr)) break;
                ++lo; gl = gr;
            }
            res = s_lut[lo];
        }
        os[k] = res;
    }
}

// ---------------------------------------------------------------------------
extern "C" void kernel_launch(void* const* d_in, const int* in_sizes, int n_in,
                              void* d_out, int out_size)
{
    const float* x = (const float*)d_in[0];
    const float* h = (const float*)d_in[1];
    const float* d = (const float*)d_in[2];
    const float* T = (const float*)d_in[3];
    const float* b = (const float*)d_in[4];
    float* out = (float*)d_out;
    int n  = in_sizes[0];
    int n4 = n >> 2;

    cudaFuncSetAttribute(ps_act,
                         cudaFuncAttributeMaxDynamicSharedMemorySize, SMEM_BYTES);

    ps_act<<<152, 1024, SMEM_BYTES>>>(h, d, T, b,
                                      (const float4*)x, (float4*)out,
                                      n4, x, out, n);
}

// round 17
// speedup vs baseline: 1.2094x; 1.0862x over previous
#include <cuda_runtime.h>

#define NBINS   8192
#define NSIDE   2048
#define N_LEV   1024
#define XMIN_F  (-4.25f)
#define XMAX_F  (4.25f)

// Round-nearest magic quantizer: j = float_bits(fmaf(xc, SCALE, OFFC)) & 0x3FFFFF
// Bin j covers v = x*SCALE + NBINS/2 in (j-0.5, j+0.5); prep edges use the
// same convention with +-0.25*W widening to absorb all fp slop.
#define SCALE_F ((float)NBINS / (XMAX_F - XMIN_F))
#define OFFC_F  (12582912.0f + (float)(NBINS / 2))

// ---------------------------------------------------------------------------
// Exact reference nearest-index (searchsorted 'left' + abs-distance compare).
// ---------------------------------------------------------------------------
__device__ __forceinline__ int nidx_exact_s(float x, const float* __restrict__ grid)
{
    int l = 0, r = N_LEV;                 // first i with grid[i] >= x
    while (l < r) {
        int m = (l + r) >> 1;
        if (grid[m] < x) l = m + 1; else r = m;
    }
    int idx = l < 1 ? 1 : (l > N_LEV - 1 ? N_LEV - 1 : l);
    float left  = grid[idx - 1];
    float right = grid[idx];
    return (fabsf(x - left) < fabsf(x - right)) ? idx - 1 : idx;
}

// Monotone walk form of nidx (identical result; cheap for advancing edges).
__device__ __forceinline__ int nidx_walk(float x, int idx,
                                         const float* __restrict__ grid)
{
    while (idx < N_LEV - 1 &&
           !(fabsf(x - grid[idx]) < fabsf(x - grid[idx + 1])))
        ++idx;
    return idx;
}

// Exact largest float x for which the reference picks the left level of the
// pair (l, r): fp bisection on the monotone predicate |x-l| < |x-r|.
__device__ __forceinline__ float thr_exact(float l, float r)
{
    if (!(l < r)) return __uint_as_float(0xFF800000u);  // -inf: always right
    float a = l, c = r;
    for (int it = 0; it < 64; ++it) {
        float m = 0.5f * (a + c);
        if (!(m > a && m < c)) break;                   // adjacent -> done
        if (fabsf(m - l) < fabsf(m - r)) a = m; else c = m;
    }
    return a;
}

// smem: 4B hot table + 16B side table + grid + lut (+ side counter)
#define SMEM_BYTES (NBINS * 4 + NSIDE * 16 + 2 * N_LEV * 4 + 16)

// ---------------------------------------------------------------------------
// Single fused kernel, 1 CTA/SM. Prologue per CTA:
//   1) grid = h[:,0]; lut[i] = chain output (exact reference semantics)
//   2) hot table s_out: pure bin -> final f32 output;
//      non-pure bin -> 0xFFC00000|si (negative-NaN space; legit outputs in
//      [-0.1, 8] can never alias). Side slot si from a SHARED atomic counter
//      (slot content is a pure function of the bin -> deterministic output).
//      <=1023 thresholds, each in <=2 widened bins -> <=2046 side slots.
//   s_side[si] = {thr_bits, outL_f32, outR_f32, flag}:
//      flag=0: (x <= thr) ? outL : outR   (thr exact via bisection)
//      flag=1: >=2 boundaries (rare) -> bounded walk; outL slot = lo|hi<<16
// Main loop: hot path = LDS.32; side path = PREDICATED LDS.128 (~12% lanes,
// predicated-off lanes consume no crossbar phases). One walk-fixup branch
// per 8 elements.
// ---------------------------------------------------------------------------
__global__ void __launch_bounds__(1024, 1)
ps_act(const float* __restrict__ h,  const float* __restrict__ d,
       const float* __restrict__ T,  const float* __restrict__ bscal,
       const float4* __restrict__ xin, float4* __restrict__ oout,
       int n4, const float* __restrict__ xs, float* __restrict__ os, int n)
{
    extern __shared__ unsigned char smem_raw[];
    unsigned* const s_out  = (unsigned*)smem_raw;
    uint4*    const s_side = (uint4*)(s_out + NBINS);
    float*    const s_grid = (float*)(s_side + NSIDE);
    float*    const s_lut  = s_grid + N_LEV;
    int*      const s_cnt  = (int*)(s_lut + N_LEV);

    const int t0 = threadIdx.x;               // 1024 threads == N_LEV

    // ---- Prologue 1: grid + lut -------------------------------------------
    {
        if (t0 == 0) *s_cnt = 0;
        float hv[9];
#pragma unroll
        for (int t = 0; t < 9; ++t) hv[t] = h[t0 * 9 + t];  // independent loads
        float v = hv[0];
        s_grid[t0] = v;
        float out = 0.0f;
#pragma unroll
        for (int t = 1; t <= 8; ++t) {
            if (v - T[t] >= 0.0f) out += d[t];
            if (t != 8) v = hv[t + 1];
        }
        s_lut[t0] = out - bscal[0];
    }
    __syncthreads();

    // ---- Prologue 2: tables (search once, then walk) ----------------------
    {
        const float W   = (XMAX_F - XMIN_F) / (float)NBINS;
        const int   BPT = NBINS / 1024;       // 8 contiguous bins per thread
        const int   j0  = t0 * BPT;

        int lo = nidx_exact_s(XMIN_F + ((float)j0 - 0.75f) * W, s_grid);
#pragma unroll 1
        for (int j = j0; j < j0 + BPT; ++j) {
            float eRw = XMIN_F + ((float)j + 0.75f) * W;
            int hi = nidx_walk(eRw, lo, s_grid);
            if (hi == lo) {
                s_out[j] = __float_as_uint(s_lut[lo]);   // pure: direct output
            } else {
                int si = atomicAdd(s_cnt, 1);            // <= 2046 < NSIDE
                uint4 rec;
                if (hi == lo + 1) {
                    rec.x = __float_as_uint(thr_exact(s_grid[lo], s_grid[hi]));
                    rec.y = __float_as_uint(s_lut[lo]);
                    rec.z = __float_as_uint(s_lut[hi]);
                    rec.w = 0u;
                } else {
                    rec.x = 0xFF800000u;                 // -inf: res=rec.z pre-walk
                    rec.y = (unsigned)lo | ((unsigned)hi << 16);
                    rec.z = 0u;
                    rec.w = 1u;
                }
                s_side[si] = rec;
                s_out[j] = 0xFFC00000u | (unsigned)si;
            }
            float eLn = XMIN_F + ((float)(j + 1) - 0.75f) * W;
            lo = nidx_walk(eLn, lo, s_grid);             // next bin's lo
        }
    }
    __syncthreads();

    // ---- Main loop --------------------------------------------------------
    const int tid = blockIdx.x * blockDim.x + t0;
    const int nt  = gridDim.x * blockDim.x;

    int i = tid;
    for (; i + nt < n4; i += 2 * nt) {
        float4 a = xin[i];
        float4 c = xin[i + nt];
        float xv[8] = {a.x, a.y, a.z, a.w, c.x, c.y, c.z, c.w};
        unsigned uv[8];
#pragma unroll
        for (int e = 0; e < 8; ++e) {
            float xc = fmaxf(xv[e], XMIN_F);                      // FMNMX
            int bits = __float_as_int(fmaf(xc, SCALE_F, OFFC_F)); // FFMA
            int j = bits & 0x3FFFFF;                              // LOP3
            j = j > NBINS - 1 ? NBINS - 1 : j;                    // IMNMX
            uv[e] = s_out[j];                                     // LDS.32
        }
        float rv[8];
        unsigned wv[8];
        unsigned anyw = 0u;
#pragma unroll
        for (int e = 0; e < 8; ++e) {
            unsigned u = uv[e];
            // default: pure bin, thr=+inf so selection picks rec.y = u
            uint4 rec = make_uint4(0x7F800000u, u, u, 0u);
            if (u >= 0xFFC00000u)                       // ~12% of lanes
                rec = s_side[u & (NSIDE - 1u)];         // @P LDS.128
            rv[e] = (xv[e] <= __uint_as_float(rec.x))
                        ? __uint_as_float(rec.y)
                        : __uint_as_float(rec.z);       // FSETP+FSEL
            wv[e] = rec.w ? rec.y : 0u;                 // SEL
            anyw |= rec.w;                              // LOP
        }
        if (anyw) {                                     // one branch per 8
#pragma unroll
            for (int e = 0; e < 8; ++e) {
                if (wv[e]) {
                    int lo = (int)(wv[e] & 0xFFFFu);
                    int hi = (int)(wv[e] >> 16);
                    float gl = s_grid[lo];
                    while (lo < hi) {
                        float gr = s_grid[lo + 1];
                        if (fabsf(xv[e] - gl) < fabsf(xv[e] - gr)) break;
                        ++lo; gl = gr;                  // exact tie-break
                    }
                    rv[e] = s_lut[lo];
                }
            }
        }
        oout[i]      = make_float4(rv[0], rv[1], rv[2], rv[3]);
        oout[i + nt] = make_float4(rv[4], rv[5], rv[6], rv[7]);
    }
    if (i < n4) {
        float4 a = xin[i];
        float xv[4] = {a.x, a.y, a.z, a.w};
        float rv[4];
#pragma unroll
        for (int e = 0; e < 4; ++e) {
            float xc = fmaxf(xv[e], XMIN_F);
            int bits = __float_as_int(fmaf(xc, SCALE_F, OFFC_F));
            int j = bits & 0x3FFFFF;
            j = j > NBINS - 1 ? NBINS - 1 : j;
            unsigned u = s_out[j];
            uint4 rec = make_uint4(0x7F800000u, u, u, 0u);
            if (u >= 0xFFC00000u) rec = s_side[u & (NSIDE - 1u)];
            float res = (xv[e] <= __uint_as_float(rec.x))
                            ? __uint_as_float(rec.y)
                            : __uint_as_float(rec.z);
            if (rec.w) {
                int lo = (int)(rec.y & 0xFFFFu);
                int hi = (int)(rec.y >> 16);
                float gl = s_grid[lo];
                while (lo < hi) {
                    float gr = s_grid[lo + 1];
                    if (fabsf(xv[e] - gl) < fabsf(xv[e] - gr)) break;
                    ++lo; gl = gr;
                }
                res = s_lut[lo];
            }
            rv[e] = res;
        }
        oout[i] = make_float4(rv[0], rv[1], rv[2], rv[3]);
    }

    // scalar tail (empty for this shape)
    for (int k = n4 * 4 + tid; k < n; k += nt) {
        float x = xs[k];
        float xc = fmaxf(x, XMIN_F);
        int bits = __float_as_int(fmaf(xc, SCALE_F, OFFC_F));
        int j = bits & 0x3FFFFF;
        j = j > NBINS - 1 ? NBINS - 1 : j;
        unsigned u = s_out[j];
        uint4 rec = make_uint4(0x7F800000u, u, u, 0u);
        if (u >= 0xFFC00000u) rec = s_side[u & (NSIDE - 1u)];
        float res = (x <= __uint_as_float(rec.x)) ? __uint_as_float(rec.y)
                                                  : __uint_as_float(rec.z);
        if (rec.w) {
            int lo = (int)(rec.y & 0xFFFFu);
            int hi = (int)(rec.y >> 16);
            float gl = s_grid[lo];
            while (lo < hi) {
                float gr = s_grid[lo + 1];
                if (fabsf(x - gl) < fabsf(x - gr)) break;
                ++lo; gl = gr;
            }
            res = s_lut[lo];
        }
        os[k] = res;
    }
}

// ---------------------------------------------------------------------------
extern "C" void kernel_launch(void* const* d_in, const int* in_sizes, int n_in,
                              void* d_out, int out_size)
{
    const float* x = (const float*)d_in[0];
    const float* h = (const float*)d_in[1];
    const float* d = (const float*)d_in[2];
    const float* T = (const float*)d_in[3];
    const float* b = (const float*)d_in[4];
    float* out = (float*)d_out;
    int n  = in_sizes[0];
    int n4 = n >> 2;

    cudaFuncSetAttribute(ps_act,
                         cudaFuncAttributeMaxDynamicSharedMemorySize, SMEM_BYTES);

    ps_act<<<152, 1024, SMEM_BYTES>>>(h, d, T, b,
                                      (const float4*)x, (float4*)out,
                                      n4, x, out, n);
}